// round 12
// baseline (speedup 1.0000x reference)
#include <cuda_runtime.h>
#include <cuda_bf16.h>
#include <cstring>

#define Bz 32
#define Sz 64
#define Tz 64
#define Ez 512
#define Hz 1024
#define VTz 32000

// ---------------- device scratch (no dynamic alloc allowed) ----------------
__device__ float g_enc_out[Bz * Sz * Hz];     // encoder hidden states (B,S,H)
__device__ float g_encpart[Bz * Sz * Hz];     // enc_out @ Wa2^T + attn_b
__device__ float g_h[2][Bz * Hz];             // double-buffered hidden
__device__ float g_c[Bz * Hz];                // cell state (in-place safe)
__device__ float g_hpart[Bz * Hz];            // h @ Wa1^T
__device__ float g_scores[Bz * Sz];
__device__ float g_xin[Bz * (Ez + Hz)];       // decoder lstm input [emb | ctx]
__device__ float g_hall[(Tz - 1) * Bz * Hz];  // all decoder h_t for final GEMM

typedef unsigned long long u64;

// packed dual-FMA (sm_100+): 2x fp32 MAC per instruction
__device__ __forceinline__ void fma2(u64 &d, u64 a, u64 b) {
    asm("fma.rn.f32x2 %0, %1, %2, %0;" : "+l"(d) : "l"(a), "l"(b));
}
__device__ __forceinline__ float2 up(u64 v) {
    float2 t; memcpy(&t, &v, 8); return t;
}
__device__ __forceinline__ u64 pk(float x, float y) {
    float2 t = make_float2(x, y); u64 r; memcpy(&r, &t, 8); return r;
}
__device__ __forceinline__ float sigf(float x) { return 1.0f / (1.0f + __expf(-x)); }
__device__ __forceinline__ float tanha(float x) {
    float y; asm("tanh.approx.f32 %0, %1;" : "=f"(y) : "f"(x)); return y;
}

// ---------------------------------------------------------------------------
// init: zero h0, c0 and the t=0 output slice (out is poisoned by harness)
// ---------------------------------------------------------------------------
__global__ void k_init(float *__restrict__ out) {
    int idx = blockIdx.x * blockDim.x + threadIdx.x;
    int stride = gridDim.x * blockDim.x;
    for (int i = idx; i < Bz * Hz; i += stride) {
        g_h[0][i] = 0.f;
        g_c[i] = 0.f;
    }
    for (int i = idx; i < Bz * VTz; i += stride) {
        int bb = i / VTz, vv = i - bb * VTz;
        out[(size_t)bb * Tz * VTz + vv] = 0.f;
    }
}

// ---------------------------------------------------------------------------
// one LSTM step: thread = (batch lane, gate column j), computes all 4 gates.
// block 256 thr = 32 lanes x 8 j-warps, grid 128 -> H=1024 columns.
// mode 0: encoder (x = enc_emb[src[b][step]]), also writes g_enc_out
// mode 1: decoder (x = g_xin), also writes g_hall[step]
// ---------------------------------------------------------------------------
__global__ void __launch_bounds__(256) k_lstm(
    const float *__restrict__ emb, const int *__restrict__ tok,
    const float *__restrict__ Wih, const float *__restrict__ Whh,
    const float *__restrict__ bih, const float *__restrict__ bhh,
    int Kx, int par, int mode, int step) {
    __shared__ float xs[32][260];  // padded: conflict-free LDS.128
    __shared__ const float *rowp[32];
    int tid = threadIdx.x, lane = tid & 31, w = tid >> 5;
    int j = blockIdx.x * 8 + w;
    u64 a0 = 0, a1 = 0, a2 = 0, a3 = 0;
    const float *hin = g_h[par];

    for (int seg = 0; seg < 2; seg++) {
        const float *Wb = seg ? Whh : Wih;
        int K = seg ? Hz : Kx;
        __syncthreads();
        if (tid < 32) {
            if (seg)
                rowp[tid] = hin + tid * Hz;
            else if (mode == 0)
                rowp[tid] = emb + (size_t)tok[tid * Sz + step] * Ez;
            else
                rowp[tid] = g_xin + (size_t)tid * (Ez + Hz);
        }
        const float *w0 = Wb + (size_t)(0 * Hz + j) * K;
        const float *w1 = Wb + (size_t)(1 * Hz + j) * K;
        const float *w2 = Wb + (size_t)(2 * Hz + j) * K;
        const float *w3 = Wb + (size_t)(3 * Hz + j) * K;
        for (int k0 = 0; k0 < K; k0 += 256) {
            __syncthreads();
            for (int i = tid; i < 32 * 64; i += 256) {
                int bb = i >> 6, kk = i & 63;
                *(float4 *)&xs[bb][kk * 4] = *(const float4 *)(rowp[bb] + k0 + kk * 4);
            }
            __syncthreads();
            const ulonglong2 *p0 = (const ulonglong2 *)(w0 + k0);
            const ulonglong2 *p1 = (const ulonglong2 *)(w1 + k0);
            const ulonglong2 *p2 = (const ulonglong2 *)(w2 + k0);
            const ulonglong2 *p3 = (const ulonglong2 *)(w3 + k0);
#pragma unroll 8
            for (int kk = 0; kk < 64; kk++) {
                ulonglong2 xv = *(const ulonglong2 *)&xs[lane][kk * 4];
                ulonglong2 q;
                q = __ldg(p0 + kk); fma2(a0, xv.x, q.x); fma2(a0, xv.y, q.y);
                q = __ldg(p1 + kk); fma2(a1, xv.x, q.x); fma2(a1, xv.y, q.y);
                q = __ldg(p2 + kk); fma2(a2, xv.x, q.x); fma2(a2, xv.y, q.y);
                q = __ldg(p3 + kk); fma2(a3, xv.x, q.x); fma2(a3, xv.y, q.y);
            }
        }
    }
    float2 t0 = up(a0), t1 = up(a1), t2 = up(a2), t3 = up(a3);
    float gi = t0.x + t0.y + bih[j] + bhh[j];
    float gf = t1.x + t1.y + bih[Hz + j] + bhh[Hz + j];
    float gg = t2.x + t2.y + bih[2 * Hz + j] + bhh[2 * Hz + j];
    float go = t3.x + t3.y + bih[3 * Hz + j] + bhh[3 * Hz + j];
    int idx = lane * Hz + j;
    float cn = sigf(gf) * g_c[idx] + sigf(gi) * tanhf(gg);
    g_c[idx] = cn;
    float hn = sigf(go) * tanhf(cn);
    g_h[par ^ 1][idx] = hn;
    if (mode == 0)
        g_enc_out[((size_t)lane * Sz + step) * Hz + j] = hn;
    else
        g_hall[((size_t)step * Bz + lane) * Hz + j] = hn;
}

// ---------------------------------------------------------------------------
// hpart[b][j] = sum_k h[b][k] * attn_W[j][k]  (first-H half of attn_W rows)
// ---------------------------------------------------------------------------
__global__ void __launch_bounds__(256) k_hpart(const float *__restrict__ attn_W, int par) {
    __shared__ float xs[32][260];
    int tid = threadIdx.x, lane = tid & 31, w = tid >> 5;
    int j = blockIdx.x * 8 + w;
    const float *hin = g_h[par];
    const float *wr = attn_W + (size_t)j * (2 * Hz);
    u64 acc = 0;
    for (int k0 = 0; k0 < Hz; k0 += 256) {
        __syncthreads();
        for (int i = tid; i < 32 * 64; i += 256) {
            int bb = i >> 6, kk = i & 63;
            *(float4 *)&xs[bb][kk * 4] =
                *(const float4 *)(hin + (size_t)bb * Hz + k0 + kk * 4);
        }
        __syncthreads();
        const ulonglong2 *p = (const ulonglong2 *)(wr + k0);
#pragma unroll 8
        for (int kk = 0; kk < 64; kk++) {
            ulonglong2 xv = *(const ulonglong2 *)&xs[lane][kk * 4];
            ulonglong2 q = __ldg(p + kk);
            fma2(acc, xv.x, q.x);
            fma2(acc, xv.y, q.y);
        }
    }
    float2 t = up(acc);
    g_hpart[lane * Hz + j] = t.x + t.y;
}

// ---------------------------------------------------------------------------
// scores[b][s] = sum_j tanh(hpart[b][j] + encpart[b][s][j]) * v[j]
// one warp per (b,s) pair; MUFU-pipe tanh.approx
// ---------------------------------------------------------------------------
__global__ void __launch_bounds__(256) k_score(const float *__restrict__ v) {
    int w = blockIdx.x * 8 + (threadIdx.x >> 5);
    int lane = threadIdx.x & 31;
    int b = w >> 6, s = w & 63;
    const float *ep = g_encpart + ((size_t)b * Sz + s) * Hz;
    const float *hp = g_hpart + (size_t)b * Hz;
    float acc = 0.f;
    for (int k = lane * 4; k < Hz; k += 128) {
        float4 e = *(const float4 *)(ep + k);
        float4 h = *(const float4 *)(hp + k);
        float4 vv = *(const float4 *)(v + k);
        acc += tanha(h.x + e.x) * vv.x + tanha(h.y + e.y) * vv.y +
               tanha(h.z + e.z) * vv.z + tanha(h.w + e.w) * vv.w;
    }
#pragma unroll
    for (int o = 16; o; o >>= 1) acc += __shfl_xor_sync(0xffffffffu, acc, o);
    if (lane == 0) g_scores[b * Sz + s] = acc;
}

// ---------------------------------------------------------------------------
// softmax over S, context = attn @ enc_out, xin = [dec_emb[tok] | ctx]
// one block per batch element
// ---------------------------------------------------------------------------
__global__ void __launch_bounds__(256) k_ctx(const float *__restrict__ dec_emb,
                                             const int *__restrict__ tgt, int d) {
    __shared__ float sm[64];
    int b = blockIdx.x, tid = threadIdx.x;
    if (tid < 64) sm[tid] = g_scores[b * Sz + tid];
    __syncthreads();
    if (tid == 0) {
        float m = sm[0];
        for (int i = 1; i < 64; i++) m = fmaxf(m, sm[i]);
        float ssum = 0.f;
        for (int i = 0; i < 64; i++) {
            float e = __expf(sm[i] - m);
            sm[i] = e;
            ssum += e;
        }
        float inv = 1.0f / ssum;
        for (int i = 0; i < 64; i++) sm[i] *= inv;
    }
    __syncthreads();
    const float *eb = g_enc_out + (size_t)b * Sz * Hz;
    int h0 = tid * 4;
    float4 acc = make_float4(0.f, 0.f, 0.f, 0.f);
    for (int s = 0; s < 64; s++) {
        float a = sm[s];
        float4 e = *(const float4 *)(eb + (size_t)s * Hz + h0);
        acc.x += a * e.x;
        acc.y += a * e.y;
        acc.z += a * e.z;
        acc.w += a * e.w;
    }
    *(float4 *)(g_xin + (size_t)b * (Ez + Hz) + Ez + h0) = acc;
    if (tid < Ez / 4) {
        int tk = tgt[b * Tz + d];
        *(float4 *)(g_xin + (size_t)b * (Ez + Hz) + tid * 4) =
            *(const float4 *)(dec_emb + (size_t)tk * Ez + tid * 4);
    }
}

// ---------------------------------------------------------------------------
// SGEMM (NT): C[r][n] = bias[n] + sum_k A[r][k]*Bm[n][k]
// BM=BN=64, BK=16, 256 thr, 4x4 micro-tile, paired-k f32x2 accumulators.
// mode 0: A=g_enc_out -> g_encpart   (attention precompute)
// mode 1: A=g_hall    -> out, remapped (b, t+1, vocab)   (final fc)
// ---------------------------------------------------------------------------
__global__ void __launch_bounds__(256) k_sgemm(
    int M, int N, int K,
    const float *__restrict__ Bm, int ldb,
    const float *__restrict__ bias,
    float *__restrict__ outp, int mode) {
    __shared__ u64 As2[8 * 64];
    __shared__ u64 Bs2[8 * 64];
    const float *A = mode ? g_hall : g_enc_out;
    int tid = threadIdx.x;
    int col0 = blockIdx.x * 64, row0 = blockIdx.y * 64;
    int m = tid >> 2, kq = tid & 3;
    int tn = tid & 15, tr = tid >> 4;
    u64 acc[16];
#pragma unroll
    for (int i = 0; i < 16; i++) acc[i] = 0ull;

    for (int k0 = 0; k0 < K; k0 += 16) {
        __syncthreads();
        {
            int r = row0 + m;
            float4 v = make_float4(0.f, 0.f, 0.f, 0.f);
            if (r < M) v = *(const float4 *)(A + (size_t)r * Hz + k0 + kq * 4);
            As2[(2 * kq) * 64 + m] = pk(v.x, v.y);
            As2[(2 * kq + 1) * 64 + m] = pk(v.z, v.w);
            float4 u = *(const float4 *)(Bm + (size_t)(col0 + m) * ldb + k0 + kq * 4);
            Bs2[(2 * kq) * 64 + m] = pk(u.x, u.y);
            Bs2[(2 * kq + 1) * 64 + m] = pk(u.z, u.w);
        }
        __syncthreads();
#pragma unroll
        for (int kp = 0; kp < 8; kp++) {
            u64 a2[4], b2[4];
            *(ulonglong2 *)&a2[0] = *(const ulonglong2 *)&As2[kp * 64 + tr * 4];
            *(ulonglong2 *)&a2[2] = *(const ulonglong2 *)&As2[kp * 64 + tr * 4 + 2];
            *(ulonglong2 *)&b2[0] = *(const ulonglong2 *)&Bs2[kp * 64 + tn * 4];
            *(ulonglong2 *)&b2[2] = *(const ulonglong2 *)&Bs2[kp * 64 + tn * 4 + 2];
#pragma unroll
            for (int i = 0; i < 4; i++)
#pragma unroll
                for (int jj = 0; jj < 4; jj++)
                    fma2(acc[i * 4 + jj], a2[i], b2[jj]);
        }
    }
#pragma unroll
    for (int i = 0; i < 4; i++) {
        int row = row0 + tr * 4 + i;
        if (row >= M) continue;
#pragma unroll
        for (int jj = 0; jj < 4; jj++) {
            int col = col0 + tn * 4 + jj;
            float2 t = up(acc[i * 4 + jj]);
            float val = t.x + t.y + bias[col];
            if (mode == 0) {
                g_encpart[(size_t)row * Hz + col] = val;
            } else {
                int st = row >> 5, bb = row & 31;
                outp[((size_t)bb * Tz + (st + 1)) * VTz + col] = val;
            }
        }
    }
}

// ---------------------------------------------------------------------------
extern "C" void kernel_launch(void* const* d_in, const int* in_sizes, int n_in,
                              void* d_out, int out_size) {
    const int   *src     = (const int *)d_in[0];
    const int   *tgt     = (const int *)d_in[1];
    const float *enc_emb = (const float *)d_in[2];
    const float *enc_Wih = (const float *)d_in[3];
    const float *enc_Whh = (const float *)d_in[4];
    const float *enc_bih = (const float *)d_in[5];
    const float *enc_bhh = (const float *)d_in[6];
    const float *dec_emb = (const float *)d_in[7];
    const float *attn_W  = (const float *)d_in[8];
    const float *attn_b  = (const float *)d_in[9];
    const float *v_W     = (const float *)d_in[10];
    const float *dec_Wih = (const float *)d_in[11];
    const float *dec_Whh = (const float *)d_in[12];
    const float *dec_bih = (const float *)d_in[13];
    const float *dec_bhh = (const float *)d_in[14];
    const float *fc_W    = (const float *)d_in[15];
    const float *fc_b    = (const float *)d_in[16];
    float *out = (float *)d_out;

    k_init<<<512, 256>>>(out);

    // encoder: 64 sequential LSTM steps
    for (int s = 0; s < Sz; s++)
        k_lstm<<<128, 256>>>(enc_emb, src, enc_Wih, enc_Whh, enc_bih, enc_bhh,
                             Ez, s & 1, 0, s);

    // step-invariant attention precompute: encpart = enc_out @ Wa2^T + attn_b
    k_sgemm<<<dim3(Hz / 64, (Bz * Sz) / 64), 256>>>(
        Bz * Sz, Hz, Hz, attn_W + Hz, 2 * Hz, attn_b, nullptr, 0);

    // decoder: 63 teacher-forced steps
    for (int d = 0; d < Tz - 1; d++) {
        k_hpart<<<128, 256>>>(attn_W, d & 1);
        k_score<<<256, 256>>>(v_W);
        k_ctx<<<Bz, 256>>>(dec_emb, tgt, d);
        k_lstm<<<128, 256>>>(nullptr, nullptr, dec_Wih, dec_Whh, dec_bih,
                             dec_bhh, Ez + Hz, d & 1, 1, d);
    }

    // one big output projection: (63*32) x 32000 x 1024
    k_sgemm<<<dim3(VTz / 64, ((Tz - 1) * Bz + 63) / 64), 256>>>(
        (Tz - 1) * Bz, VTz, Hz, fc_W, Hz, fc_b, out, 1);
}